// round 2
// baseline (speedup 1.0000x reference)
#include <cuda_runtime.h>

// x: (32, 256, 256, 16) float32, contiguous.
// p[h][w] = mean over b (32) and c (16) of x[b][h][w][c]  -> 512-way reduction
// out = (p >= ALPHA) ? x * ALPHA / p : 1 - beta*(1-x),  beta = (1-ALPHA)/(1-p)
// Both branches are affine in x: out = a*x + c with per-(h,w) constants.
//
// One block per (h, w-quarter): 64 w positions, 16 channels, 32 batches.
// 256 threads: thread t owns float4 #t of the 1024-float contiguous slice
// (w_local = t>>2, channels (t&3)*4 .. +3). Pass A reduces, pass B re-reads
// (L2-hot) and applies the fused fma + store.

#define ALPHA_F 0.25f

static constexpr int B        = 32;
static constexpr int BSTRIDE4 = 256 * 256 * 16 / 4;  // batch stride in float4 units = 262144

__global__ void __launch_bounds__(256)
rescale_prob_mask_kernel(const float* __restrict__ x, float* __restrict__ out) {
    __shared__ float s_a[64];
    __shared__ float s_c[64];

    const int t  = threadIdx.x;
    const int h  = blockIdx.x >> 2;          // 0..255
    const int wq = blockIdx.x & 3;           // 0..3 (quarter of w)

    // Base offset (in float4 units) of this block's slice within one batch.
    const size_t base4 = ((size_t)h * 4096 + (size_t)wq * 1024) >> 2;  // floats->float4
    const size_t idx0  = base4 + (size_t)t;

    const float4* __restrict__ x4 = (const float4*)x;
    float4*       __restrict__ o4 = (float4*)out;

    // ---- Pass A: reduce over 32 batches (each thread: 4 channels of one w) ----
    float s = 0.0f;
#pragma unroll
    for (int b = 0; b < B; b++) {
        float4 v = __ldg(&x4[idx0 + (size_t)b * BSTRIDE4]);
        s += (v.x + v.y) + (v.z + v.w);
    }
    // Reduce across the 4 lanes sharing one w (lanes 4k..4k+3 of the warp).
    s += __shfl_xor_sync(0xffffffffu, s, 1);
    s += __shfl_xor_sync(0xffffffffu, s, 2);

    if ((t & 3) == 0) {
        float p = s * (1.0f / 512.0f);
        float a, c;
        if (p >= ALPHA_F) {
            a = ALPHA_F / p;
            c = 0.0f;
        } else {
            float beta = (1.0f - ALPHA_F) / (1.0f - p);
            a = beta;
            c = 1.0f - beta;
        }
        s_a[t >> 2] = a;
        s_c[t >> 2] = c;
    }
    __syncthreads();

    const float a = s_a[t >> 2];
    const float c = s_c[t >> 2];

    // ---- Pass B: re-read (L2-hot), fused affine, store ----
#pragma unroll
    for (int b = 0; b < B; b++) {
        const size_t i = idx0 + (size_t)b * BSTRIDE4;
        float4 v = x4[i];
        float4 r;
        r.x = fmaf(a, v.x, c);
        r.y = fmaf(a, v.y, c);
        r.z = fmaf(a, v.z, c);
        r.w = fmaf(a, v.w, c);
        o4[i] = r;
    }
}

extern "C" void kernel_launch(void* const* d_in, const int* in_sizes, int n_in,
                              void* d_out, int out_size) {
    const float* x   = (const float*)d_in[0];
    float*       out = (float*)d_out;
    // grid: 256 h-rows x 4 w-quarters = 1024 blocks
    rescale_prob_mask_kernel<<<1024, 256>>>(x, out);
}

// round 3
// speedup vs baseline: 1.4652x; 1.4652x over previous
#include <cuda_runtime.h>

// x: (32, 256, 256, 16) float32, contiguous.
// p[h][w] = mean over b (32) and c (16) of x[b][h][w][c]   (512-way reduction)
// out = (p >= ALPHA) ? (ALPHA/p)*x : beta*x + (1-beta),  beta = (1-ALPHA)/(1-p)
// Both branches are affine in x: out = a*x + c with per-(h,w) constants.
//
// Register-staged single-pass version (no DRAM re-read):
// one block owns a (h, w-16th) tile: 16 w x 16 c x 32 b = 32 KiB = 2048 float4.
// 256 threads; thread t holds 8 float4 in registers:
//   pos4 = t & 63  -> float4 index within one batch's contiguous 256-float slice
//                     (w_local = pos4>>2, channel group = pos4&3)
//   bgrp = t >> 6  -> batches b = bgrp*8 .. bgrp*8+7
// Pass A: sum held values, shfl across the 4 channel lanes, deterministic
// 4-way smem combine across batch groups -> p[w] -> (a, c).
// Pass B: fma on the HELD registers, store. DRAM = 256 MB total (minimum).

#define ALPHA_F 0.25f

static constexpr int BSTRIDE4 = 256 * 256 * 16 / 4;  // batch stride in float4 = 262144

__global__ void __launch_bounds__(256)
rescale_prob_mask_kernel(const float* __restrict__ x, float* __restrict__ out) {
    __shared__ float s_part[4][16];   // [batch-group][w_local]
    __shared__ float s_a[16];
    __shared__ float s_c[16];

    const int t    = threadIdx.x;
    const int pos4 = t & 63;          // float4 slot within the per-batch slice
    const int bgrp = t >> 6;          // 0..3 -> 8 batches each
    const int w    = pos4 >> 2;       // 0..15 local w

    const int h  = blockIdx.x >> 4;   // 0..255
    const int wq = blockIdx.x & 15;   // 0..15 (16-wide w chunk)

    // float4 offset of this block's slice within one batch image (4096 floats/row)
    const size_t base4 = (size_t)h * 1024 + (size_t)wq * 64;
    const size_t idx0  = base4 + (size_t)pos4 + (size_t)(bgrp * 8) * (size_t)BSTRIDE4;

    const float4* __restrict__ x4 = (const float4*)x;
    float4*       __restrict__ o4 = (float4*)out;

    // ---- Load 8 float4 into registers (8 independent LDG.128 -> high MLP) ----
    float4 v[8];
#pragma unroll
    for (int j = 0; j < 8; j++)
        v[j] = x4[idx0 + (size_t)j * BSTRIDE4];

    // ---- Pass A: reduce 512 values per w ----
    float s = 0.0f;
#pragma unroll
    for (int j = 0; j < 8; j++)
        s += (v[j].x + v[j].y) + (v[j].z + v[j].w);

    // combine the 4 channel lanes (lanes 4k..4k+3 share one w)
    s += __shfl_xor_sync(0xffffffffu, s, 1);
    s += __shfl_xor_sync(0xffffffffu, s, 2);

    if ((t & 3) == 0)
        s_part[bgrp][w] = s;          // per (batch-group, w) partial: 16c x 8b
    __syncthreads();

    if (t < 16) {
        float p = (s_part[0][t] + s_part[1][t] + s_part[2][t] + s_part[3][t])
                  * (1.0f / 512.0f);
        float a, c;
        if (p >= ALPHA_F) {
            a = ALPHA_F / p;
            c = 0.0f;
        } else {
            float beta = (1.0f - ALPHA_F) / (1.0f - p);
            a = beta;
            c = 1.0f - beta;
        }
        s_a[t] = a;
        s_c[t] = c;
    }
    __syncthreads();

    const float a = s_a[w];
    const float c = s_c[w];

    // ---- Pass B: fused affine on held registers, store ----
#pragma unroll
    for (int j = 0; j < 8; j++) {
        float4 r;
        r.x = fmaf(a, v[j].x, c);
        r.y = fmaf(a, v[j].y, c);
        r.z = fmaf(a, v[j].z, c);
        r.w = fmaf(a, v[j].w, c);
        o4[idx0 + (size_t)j * BSTRIDE4] = r;
    }
}

extern "C" void kernel_launch(void* const* d_in, const int* in_sizes, int n_in,
                              void* d_out, int out_size) {
    const float* x   = (const float*)d_in[0];
    float*       out = (float*)d_out;
    // 256 h-rows x 16 w-chunks = 4096 blocks
    rescale_prob_mask_kernel<<<4096, 256>>>(x, out);
}

// round 6
// speedup vs baseline: 1.4736x; 1.0057x over previous
#include <cuda_runtime.h>

// x: (32, 256, 256, 16) float32, contiguous.
// p[h][w] = mean over b (32) and c (16) of x[b][h][w][c]   (512-way reduction)
// out = (p >= ALPHA) ? (ALPHA/p)*x : beta*x + (1-beta),  beta = (1-ALPHA)/(1-p)
// Both branches are affine in x: out = a*x + c, per-(h,w) constants.
//
// Warp-autonomous version: NO __syncthreads, NO smem.
// One warp owns 2 w-positions (2 w x 16 c x 32 b = 1024 floats = 256 float4).
// Lane l: pos4 = l & 7   -> float4 slot within the 2w*16c = 8-float4 contiguous
//                           slice of one batch (w_local = pos4>>2)
//         bgrp = l >> 3  -> batches bgrp*8 .. bgrp*8+7  (8 float4 held in regs)
// Reduce: shfl_xor 1,2 (channel lanes) then 8,16 (batch groups) -> p for this
// lane's w. Apply fused fma to the held registers, store. Warps never wait on
// each other, so loads/stores of different warps overlap and DRAM stays busy.

#define ALPHA_F 0.25f

static constexpr int BSTRIDE4 = 256 * 256 * 16 / 4;  // batch stride in float4 = 262144

__global__ void __launch_bounds__(256)
rescale_prob_mask_kernel(const float* __restrict__ x, float* __restrict__ out) {
    const int t    = threadIdx.x;
    const int lane = t & 31;
    const int wid  = t >> 5;          // warp within block: 0..7 -> w pair

    const int pos4 = lane & 7;        // float4 slot in the 8-f4 contiguous slice
    const int bgrp = lane >> 3;       // 0..3, 8 batches each

    const int h  = blockIdx.x >> 4;   // 0..255
    const int wq = blockIdx.x & 15;   // 16-w chunk; warp owns 2 of those 16

    // float4 offset of this warp's slice within one batch image (1024 f4/row)
    const size_t base4 = (size_t)h * 1024 + (size_t)wq * 64 + (size_t)wid * 8;
    const size_t idx0  = base4 + (size_t)pos4
                       + (size_t)(bgrp * 8) * (size_t)BSTRIDE4;

    const float4* __restrict__ x4 = (const float4*)x;
    float4*       __restrict__ o4 = (float4*)out;

    // ---- Load 8 float4 into registers (streaming: no reuse) ----
    float4 v[8];
#pragma unroll
    for (int j = 0; j < 8; j++)
        v[j] = __ldcs(&x4[idx0 + (size_t)j * BSTRIDE4]);

    // ---- Warp-local reduction: 512 values per w ----
    float s = 0.0f;
#pragma unroll
    for (int j = 0; j < 8; j++)
        s += (v[j].x + v[j].y) + (v[j].z + v[j].w);

    s += __shfl_xor_sync(0xffffffffu, s, 1);   // channel lanes
    s += __shfl_xor_sync(0xffffffffu, s, 2);
    s += __shfl_xor_sync(0xffffffffu, s, 8);   // batch groups
    s += __shfl_xor_sync(0xffffffffu, s, 16);

    const float p = s * (1.0f / 512.0f);
    float a, c;
    if (p >= ALPHA_F) {
        a = ALPHA_F / p;
        c = 0.0f;
    } else {
        const float beta = (1.0f - ALPHA_F) / (1.0f - p);
        a = beta;
        c = 1.0f - beta;
    }

    // ---- Fused affine on held registers, streaming store ----
#pragma unroll
    for (int j = 0; j < 8; j++) {
        float4 r;
        r.x = fmaf(a, v[j].x, c);
        r.y = fmaf(a, v[j].y, c);
        r.z = fmaf(a, v[j].z, c);
        r.w = fmaf(a, v[j].w, c);
        __stcs(&o4[idx0 + (size_t)j * BSTRIDE4], r);
    }
}

extern "C" void kernel_launch(void* const* d_in, const int* in_sizes, int n_in,
                              void* d_out, int out_size) {
    const float* x   = (const float*)d_in[0];
    float*       out = (float*)d_out;
    // 256 h-rows x 16 w-chunks = 4096 blocks, 8 warps each (2 w per warp)
    rescale_prob_mask_kernel<<<4096, 256>>>(x, out);
}